// round 8
// baseline (speedup 1.0000x reference)
#include <cuda_runtime.h>
#include <cuda_bf16.h>

// Fixed problem constants:
//   SIGMA=8 -> 1/(2*sigma^2)=1/128, C_SIZE=512, STRIDE=8 -> 64x64 grid,
//   cood[k]=8k+4, B=16, N=512, BG_RATIO=0.15, EPS=1e-5
//   out[b, p, i*64+j], p in [0,512], fp32, [16, 513, 4096]

#define CGRID   64
#define NPTS    512
#define PCHUNK  32
#define NCHUNK  (NPTS / PCHUNK)     // 16
#define BFIX    16
#define MPIX    (CGRID * CGRID)     // 4096
#define KINV    (1.0f / 128.0f)
#define NSTAGE  2
#define BSTAGE  (BFIX / NSTAGE)     // 8 images per stage

// Static scratch (no runtime allocation allowed)
__device__ float g_psum[BFIX * NCHUNK * MPIX];   // 4 MB per-chunk partial sums
__device__ float g_pmax[BFIX * NCHUNK * MPIX];   // 4 MB per-chunk max products
__device__ float g_invt[BFIX * MPIX];            // 1/denominator per pixel

// ---------------------------------------------------------------------------
// K1: per (b, chunk, 16-row tile): partial exp-sum + max product (smem tables).
//     min-distance recovered later as -128*ln(max product).
// ---------------------------------------------------------------------------
__global__ __launch_bounds__(256)
void k_partial(const float* __restrict__ points, int b_base)
{
    const int b   = b_base + blockIdx.z;
    const int c   = blockIdx.y;
    const int i0  = blockIdx.x * 16;
    const int tid = threadIdx.x;
    const int ti  = tid >> 4;      // 0..15 row in tile
    const int jg  = tid & 15;      // owns j = jg*4 + {0..3}

    __shared__ float2 pts_s[PCHUNK];            // 256 B
    __shared__ float  Ex_s[PCHUNK * CGRID];     // 8 KB  [p][j]
    __shared__ float  Ey_s[16 * PCHUNK];        // 2 KB  [ti][p]

    const float2* ptb = (const float2*)points + b * NPTS + c * PCHUNK;
    if (tid < PCHUNK) pts_s[tid] = ptb[tid];
    __syncthreads();

    #pragma unroll
    for (int k = 0; k < (PCHUNK * CGRID) / 256; ++k) {   // 8 iters
        int idx = tid + k * 256;
        int p = idx >> 6, jj = idx & 63;
        float dx = pts_s[p].x - (float)(jj * 8 + 4);
        Ex_s[idx] = __expf(-dx * dx * KINV);
    }
    #pragma unroll
    for (int k = 0; k < (16 * PCHUNK) / 256; ++k) {      // 2 iters
        int idx = tid + k * 256;
        int ii = idx >> 5, p = idx & (PCHUNK - 1);
        float dy = pts_s[p].y - (float)((i0 + ii) * 8 + 4);
        Ey_s[idx] = __expf(-dy * dy * KINV);
    }
    __syncthreads();

    float4 sum = make_float4(0.f, 0.f, 0.f, 0.f);
    float4 mx  = make_float4(0.f, 0.f, 0.f, 0.f);
    const float4* Ex4 = (const float4*)Ex_s;

    #pragma unroll 8
    for (int p = 0; p < PCHUNK; ++p) {
        float  ey = Ey_s[ti * PCHUNK + p];
        float4 ex = Ex4[p * 16 + jg];
        float p0 = ey * ex.x;
        float p1 = ey * ex.y;
        float p2 = ey * ex.z;
        float p3 = ey * ex.w;
        sum.x += p0; sum.y += p1; sum.z += p2; sum.w += p3;
        mx.x = fmaxf(mx.x, p0); mx.y = fmaxf(mx.y, p1);
        mx.z = fmaxf(mx.z, p2); mx.w = fmaxf(mx.w, p3);
    }

    int o = (b * NCHUNK + c) * MPIX + (i0 + ti) * CGRID + jg * 4;
    *(float4*)(g_psum + o) = sum;
    *(float4*)(g_pmax + o) = mx;
}

// ---------------------------------------------------------------------------
// K2: reduce chunk partials -> invt per pixel; write background plane p=512.
// ---------------------------------------------------------------------------
__global__ __launch_bounds__(256)
void k_combine(const float* __restrict__ st_sizes, float* __restrict__ out,
               int b_base)
{
    int idx = blockIdx.x * 256 + threadIdx.x;       // over BSTAGE*1024
    int b = b_base + (idx >> 10);
    int r = idx & 1023;

    const float4* ps = (const float4*)g_psum;
    const float4* pm = (const float4*)g_pmax;
    int base = b * NCHUNK * 1024 + r;

    float4 sum = make_float4(0.f, 0.f, 0.f, 0.f);
    float4 mx  = make_float4(0.f, 0.f, 0.f, 0.f);
    #pragma unroll
    for (int c = 0; c < NCHUNK; ++c) {
        float4 s = ps[base + c * 1024];
        float4 m = pm[base + c * 1024];
        sum.x += s.x; sum.y += s.y; sum.z += s.z; sum.w += s.w;
        mx.x = fmaxf(mx.x, m.x); mx.y = fmaxf(mx.y, m.y);
        mx.z = fmaxf(mx.z, m.z); mx.w = fmaxf(mx.w, m.w);
    }

    float sc = st_sizes[b] * 0.15f;
    float ss = sc * sc;
    float4 invt, bgp;
    {
        float mind = -128.0f * __logf(fmaxf(mx.x, 1e-38f));
        float ebg = __expf(-(ss / (mind + 1e-5f)) * KINV);
        float iv = 1.0f / (sum.x + ebg); invt.x = iv; bgp.x = ebg * iv;
    }
    {
        float mind = -128.0f * __logf(fmaxf(mx.y, 1e-38f));
        float ebg = __expf(-(ss / (mind + 1e-5f)) * KINV);
        float iv = 1.0f / (sum.y + ebg); invt.y = iv; bgp.y = ebg * iv;
    }
    {
        float mind = -128.0f * __logf(fmaxf(mx.z, 1e-38f));
        float ebg = __expf(-(ss / (mind + 1e-5f)) * KINV);
        float iv = 1.0f / (sum.z + ebg); invt.z = iv; bgp.z = ebg * iv;
    }
    {
        float mind = -128.0f * __logf(fmaxf(mx.w, 1e-38f));
        float ebg = __expf(-(ss / (mind + 1e-5f)) * KINV);
        float iv = 1.0f / (sum.w + ebg); invt.w = iv; bgp.w = ebg * iv;
    }

    ((float4*)g_invt)[b * 1024 + r] = invt;
    __stcs(((float4*)out) + (b * 513 + 512) * 1024 + r, bgp);  // background plane
}

// ---------------------------------------------------------------------------
// K3: normalized writes. Block = (b, group of 8 planes) -> fully contiguous
//     128 KB output span per block, streaming stores.
// ---------------------------------------------------------------------------
#define PGRP 8

__global__ __launch_bounds__(256)
void k_write(const float* __restrict__ points, float* __restrict__ out,
             int b_base)
{
    const int b   = b_base + (blockIdx.x >> 6);
    const int pg  = blockIdx.x & 63;            // plane group: p = pg*8 + pl
    const int tid = threadIdx.x;

    __shared__ float Ex_s[PGRP][CGRID];         // 2 KB
    __shared__ float Ey_s[PGRP][CGRID];         // 2 KB

    #pragma unroll
    for (int k = 0; k < 4; ++k) {
        int idx  = tid + k * 256;               // 0..1023
        int pl   = idx >> 7;
        int rest = idx & 127;
        int t    = rest >> 6;                   // 0: Ex (x), 1: Ey (y)
        int cell = rest & 63;
        int p    = pg * PGRP + pl;
        float coord = points[(b * NPTS + p) * 2 + t];
        float d = coord - (float)(cell * 8 + 4);
        float e = __expf(-d * d * KINV);
        if (t) Ey_s[pl][cell] = e; else Ex_s[pl][cell] = e;
    }

    const float4* iv4 = (const float4*)g_invt + b * 1024;
    float4 invt[4];
    #pragma unroll
    for (int k = 0; k < 4; ++k)
        invt[k] = __ldg(iv4 + tid + k * 256);

    __syncthreads();

    float4* op = (float4*)out + ((size_t)b * 513 + pg * PGRP) * 1024;

    #pragma unroll
    for (int pl = 0; pl < PGRP; ++pl) {
        const float4* Ex4 = (const float4*)Ex_s[pl];
        #pragma unroll
        for (int k = 0; k < 4; ++k) {
            int f  = tid + k * 256;
            int i  = f >> 4;
            int jg = f & 15;
            float  ey = Ey_s[pl][i];
            float4 ex = Ex4[jg];
            float4 v;
            v.x = (ey * ex.x) * invt[k].x;
            v.y = (ey * ex.y) * invt[k].y;
            v.z = (ey * ex.z) * invt[k].z;
            v.w = (ey * ex.w) * invt[k].w;
            __stcs(op + (size_t)pl * 1024 + f, v);
        }
    }
}

// ---------------------------------------------------------------------------
// Launch: 2-stage compute/write pipeline on TWO explicitly-created
// non-blocking streams (no legacy-stream implicit-sync edges in the graph).
// Fork from the captured stream via a root event; join both at the end.
// Streams/events created lazily on the first (non-captured) correctness call.
// ---------------------------------------------------------------------------
extern "C" void kernel_launch(void* const* d_in, const int* in_sizes, int n_in,
                              void* d_out, int out_size)
{
    const float* points   = (const float*)d_in[0];   // [16, 512, 2]
    const float* st_sizes = (const float*)d_in[1];   // [16]
    float* out = (float*)d_out;                      // [16, 513, 4096]

    static cudaStream_t sA = nullptr, sB = nullptr;
    static cudaEvent_t evRoot, evC[NSTAGE], evA, evB;
    if (!sA) {
        cudaStreamCreateWithFlags(&sA, cudaStreamNonBlocking);
        cudaStreamCreateWithFlags(&sB, cudaStreamNonBlocking);
        cudaEventCreateWithFlags(&evRoot, cudaEventDisableTiming);
        for (int g = 0; g < NSTAGE; ++g)
            cudaEventCreateWithFlags(&evC[g], cudaEventDisableTiming);
        cudaEventCreateWithFlags(&evA, cudaEventDisableTiming);
        cudaEventCreateWithFlags(&evB, cudaEventDisableTiming);
    }

    // Fork both worker streams off the (captured) incoming stream.
    cudaEventRecord(evRoot, 0);
    cudaStreamWaitEvent(sA, evRoot, 0);
    cudaStreamWaitEvent(sB, evRoot, 0);

    dim3 gP(CGRID / 16, NCHUNK, BSTAGE);             // (4,16,8) = 512 blocks
    const int gC = (BSTAGE * 1024) / 256;            // 32 blocks
    const int gW = BSTAGE * (NPTS / PGRP);           // 512 blocks

    for (int g = 0; g < NSTAGE; ++g) {
        int b0 = g * BSTAGE;
        k_partial<<<gP, 256, 0, sA>>>(points, b0);
        k_combine<<<gC, 256, 0, sA>>>(st_sizes, out, b0);
        cudaEventRecord(evC[g], sA);
        cudaStreamWaitEvent(sB, evC[g], 0);
        k_write<<<gW, 256, 0, sB>>>(points, out, b0);
    }

    // Join both branches back into the captured stream.
    cudaEventRecord(evA, sA);
    cudaEventRecord(evB, sB);
    cudaStreamWaitEvent(0, evA, 0);
    cudaStreamWaitEvent(0, evB, 0);
}

// round 9
// speedup vs baseline: 1.2327x; 1.2327x over previous
#include <cuda_runtime.h>
#include <cuda_bf16.h>

// Fixed problem constants:
//   SIGMA=8 -> 1/(2*sigma^2)=1/128, C_SIZE=512, STRIDE=8 -> 64x64 grid,
//   cood[k]=8k+4, B=16, N=512, BG_RATIO=0.15, EPS=1e-5
//   out[b, p, i*64+j], p in [0,512], fp32, [16, 513, 4096]

#define CGRID   64
#define NPTS    512
#define PCHUNK  32
#define NCHUNK  (NPTS / PCHUNK)     // 16
#define BFIX    16
#define MPIX    (CGRID * CGRID)     // 4096
#define KINV    (1.0f / 128.0f)
#define PGRP    8

#define NPARTIAL 1024               // 16 img * 16 chunks * 4 i-tiles
#define NCOMBINE 64                 // 16 img * 4 quarters
#define NWRITE   1024               // 16 img * 64 plane-groups
#define NBLOCKS  (NPARTIAL + NCOMBINE + NWRITE)   // 2112

// Static scratch (no runtime allocation allowed)
__device__ float g_psum[BFIX * NCHUNK * MPIX];   // 4 MB per-chunk partial sums
__device__ float g_pmax[BFIX * NCHUNK * MPIX];   // 4 MB per-chunk max products
__device__ float g_invt[BFIX * MPIX];            // 1/denominator per pixel
__device__ int   g_pdone[BFIX];                  // partial blocks retired per image
__device__ int   g_cdone[BFIX];                  // combine blocks retired per image
__device__ int   g_wdone[BFIX];                  // write blocks retired per image

// Acquire: tid0 spins until *ctr >= target, then block-wide acquire.
__device__ __forceinline__ void spin_acquire(int* ctr, int target)
{
    if (threadIdx.x == 0) {
        while (atomicAdd(ctr, 0) < target) __nanosleep(128);
        __threadfence();
    }
    __syncthreads();
}

// Release: all threads' prior stores visible, then tid0 bumps counter.
__device__ __forceinline__ int release_add(int* ctr)
{
    __threadfence();
    __syncthreads();
    int r = -1;
    if (threadIdx.x == 0) r = atomicAdd(ctr, 1);
    return r;
}

__global__ __launch_bounds__(256)
void k_fused(const float* __restrict__ points,
             const float* __restrict__ st_sizes,
             float* __restrict__ out)
{
    const int bid = blockIdx.x;
    const int tid = threadIdx.x;

    __shared__ float sm[PCHUNK * CGRID + 16 * PCHUNK + 2 * PCHUNK]; // 10.5 KB

    if (bid < NPARTIAL) {
        // ================= PARTIAL role: (b, chunk, 16-row tile) ============
        const int b  = bid >> 6;            // image: bids for image b contiguous
        const int c  = (bid >> 2) & 15;     // chunk
        const int i0 = (bid & 3) * 16;      // i-tile base
        const int ti = tid >> 4;
        const int jg = tid & 15;

        float2* pts_s = (float2*)sm;                         // 32 float2
        float*  Ex_s  = sm + 2 * PCHUNK;                     // 2048
        float*  Ey_s  = Ex_s + PCHUNK * CGRID;               // 512

        const float2* ptb = (const float2*)points + b * NPTS + c * PCHUNK;
        if (tid < PCHUNK) pts_s[tid] = ptb[tid];
        __syncthreads();

        #pragma unroll
        for (int k = 0; k < (PCHUNK * CGRID) / 256; ++k) {   // 8 iters
            int idx = tid + k * 256;
            int p = idx >> 6, jj = idx & 63;
            float dx = pts_s[p].x - (float)(jj * 8 + 4);
            Ex_s[idx] = __expf(-dx * dx * KINV);
        }
        #pragma unroll
        for (int k = 0; k < (16 * PCHUNK) / 256; ++k) {      // 2 iters
            int idx = tid + k * 256;
            int ii = idx >> 5, p = idx & (PCHUNK - 1);
            float dy = pts_s[p].y - (float)((i0 + ii) * 8 + 4);
            Ey_s[idx] = __expf(-dy * dy * KINV);
        }
        __syncthreads();

        float4 sum = make_float4(0.f, 0.f, 0.f, 0.f);
        float4 mx  = make_float4(0.f, 0.f, 0.f, 0.f);
        const float4* Ex4 = (const float4*)Ex_s;

        #pragma unroll 8
        for (int p = 0; p < PCHUNK; ++p) {
            float  ey = Ey_s[ti * PCHUNK + p];
            float4 ex = Ex4[p * 16 + jg];
            float p0 = ey * ex.x;
            float p1 = ey * ex.y;
            float p2 = ey * ex.z;
            float p3 = ey * ex.w;
            sum.x += p0; sum.y += p1; sum.z += p2; sum.w += p3;
            mx.x = fmaxf(mx.x, p0); mx.y = fmaxf(mx.y, p1);
            mx.z = fmaxf(mx.z, p2); mx.w = fmaxf(mx.w, p3);
        }

        int o = (b * NCHUNK + c) * MPIX + (i0 + ti) * CGRID + jg * 4;
        *(float4*)(g_psum + o) = sum;
        *(float4*)(g_pmax + o) = mx;

        release_add(&g_pdone[b]);
    }
    else if (bid < NPARTIAL + NCOMBINE) {
        // ================= COMBINE role: (b, quarter of pixels) =============
        const int idx = bid - NPARTIAL;
        const int b   = idx >> 2;
        const int q   = idx & 3;
        const int r   = q * 256 + tid;       // float4 index within image, 0..1023

        spin_acquire(&g_pdone[b], 64);       // all partials of image b done

        const float4* ps = (const float4*)g_psum;
        const float4* pm = (const float4*)g_pmax;
        int base = b * NCHUNK * 1024 + r;

        float4 sum = make_float4(0.f, 0.f, 0.f, 0.f);
        float4 mx  = make_float4(0.f, 0.f, 0.f, 0.f);
        #pragma unroll
        for (int c = 0; c < NCHUNK; ++c) {
            float4 s = ps[base + c * 1024];
            float4 m = pm[base + c * 1024];
            sum.x += s.x; sum.y += s.y; sum.z += s.z; sum.w += s.w;
            mx.x = fmaxf(mx.x, m.x); mx.y = fmaxf(mx.y, m.y);
            mx.z = fmaxf(mx.z, m.z); mx.w = fmaxf(mx.w, m.w);
        }

        float sc = st_sizes[b] * 0.15f;
        float ss = sc * sc;
        float4 invt, bgp;
        {
            float mind = -128.0f * __logf(fmaxf(mx.x, 1e-38f));
            float ebg = __expf(-(ss / (mind + 1e-5f)) * KINV);
            float iv = 1.0f / (sum.x + ebg); invt.x = iv; bgp.x = ebg * iv;
        }
        {
            float mind = -128.0f * __logf(fmaxf(mx.y, 1e-38f));
            float ebg = __expf(-(ss / (mind + 1e-5f)) * KINV);
            float iv = 1.0f / (sum.y + ebg); invt.y = iv; bgp.y = ebg * iv;
        }
        {
            float mind = -128.0f * __logf(fmaxf(mx.z, 1e-38f));
            float ebg = __expf(-(ss / (mind + 1e-5f)) * KINV);
            float iv = 1.0f / (sum.z + ebg); invt.z = iv; bgp.z = ebg * iv;
        }
        {
            float mind = -128.0f * __logf(fmaxf(mx.w, 1e-38f));
            float ebg = __expf(-(ss / (mind + 1e-5f)) * KINV);
            float iv = 1.0f / (sum.w + ebg); invt.w = iv; bgp.w = ebg * iv;
        }

        ((float4*)g_invt)[b * 1024 + r] = invt;
        __stcs(((float4*)out) + (b * 513 + 512) * 1024 + r, bgp);

        release_add(&g_cdone[b]);
    }
    else {
        // ================= WRITE role: (b, group of 8 planes) ===============
        const int idx = bid - NPARTIAL - NCOMBINE;
        const int b   = idx >> 6;
        const int pg  = idx & 63;

        float (*Ex_s)[CGRID] = (float (*)[CGRID])sm;            // [8][64]
        float (*Ey_s)[CGRID] = (float (*)[CGRID])(sm + PGRP * CGRID);

        // Fill per-plane Ex/Ey rows (independent of partial/combine data).
        #pragma unroll
        for (int k = 0; k < 4; ++k) {
            int ii   = tid + k * 256;           // 0..1023
            int pl   = ii >> 7;
            int rest = ii & 127;
            int t    = rest >> 6;               // 0: Ex (x), 1: Ey (y)
            int cell = rest & 63;
            int p    = pg * PGRP + pl;
            float coord = points[(b * NPTS + p) * 2 + t];
            float d = coord - (float)(cell * 8 + 4);
            float e = __expf(-d * d * KINV);
            if (t) Ey_s[pl][cell] = e; else Ex_s[pl][cell] = e;
        }

        spin_acquire(&g_cdone[b], 4);           // invt of image b ready
        // (spin_acquire ends in __syncthreads -> smem fill also synced)

        float4 invt[4];
        #pragma unroll
        for (int k = 0; k < 4; ++k)
            invt[k] = ((const float4*)g_invt)[b * 1024 + tid + k * 256];

        float4* op = (float4*)out + ((size_t)b * 513 + pg * PGRP) * 1024;

        #pragma unroll
        for (int pl = 0; pl < PGRP; ++pl) {
            const float4* Ex4 = (const float4*)Ex_s[pl];
            #pragma unroll
            for (int k = 0; k < 4; ++k) {
                int f  = tid + k * 256;
                int i  = f >> 4;
                int jg = f & 15;
                float  ey = Ey_s[pl][i];
                float4 ex = Ex4[jg];
                float4 v;
                v.x = (ey * ex.x) * invt[k].x;
                v.y = (ey * ex.y) * invt[k].y;
                v.z = (ey * ex.z) * invt[k].z;
                v.w = (ey * ex.w) * invt[k].w;
                __stcs(op + (size_t)pl * 1024 + f, v);
            }
        }

        // Last write block of image b resets its counters for the next replay.
        int r = release_add(&g_wdone[b]);
        if (threadIdx.x == 0 && r == 63) {
            atomicExch(&g_pdone[b], 0);
            atomicExch(&g_cdone[b], 0);
            atomicExch(&g_wdone[b], 0);
        }
    }
}

// ---------------------------------------------------------------------------
extern "C" void kernel_launch(void* const* d_in, const int* in_sizes, int n_in,
                              void* d_out, int out_size)
{
    const float* points   = (const float*)d_in[0];   // [16, 512, 2]
    const float* st_sizes = (const float*)d_in[1];   // [16]
    float* out = (float*)d_out;                      // [16, 513, 4096]

    k_fused<<<NBLOCKS, 256>>>(points, st_sizes, out);
}